// round 15
// baseline (speedup 1.0000x reference)
#include <cuda_runtime.h>
#include <cuda_bf16.h>
#include <math.h>

// Fused quantized LeNet, round 15: column-pair FFMA2 in BOTH convs.
// conv1: input rows stored interleaved XI[2k]={x[k]}, XI[2k+1]={x[k+12]}
//   (32 floats/row, zero duplication) so conv-col pairs {c,c+12} (= pooled
//   pairs {p,p+6}) take x operands as native aligned u64 pairs from LDS.128.
//   Per row: 3 LDS + 10 pk + 20 FFMA2 vs scalar 2 LDS + 40 FFMA.
// conv2: R14's bank-fixed column-pair FFMA2 (proven, ties R5 at 36.9us).
// Conv per-product clip never fires (|w*x| <= ~13 << 255): convs pure FMA.

#define B        1024
#define NTHR     160

typedef unsigned long long u64;

__device__ __forceinline__ float q8(float x) {
    return rintf(x * 256.0f) * 0.00390625f;   // round-half-even, scale 2^-8
}
__device__ __forceinline__ float clipf(float x) {
    return fminf(fmaxf(x, -256.0f), 255.0f);
}
__device__ __forceinline__ u64 pk(float lo, float hi) {
    u64 r; asm("mov.b64 %0,{%1,%2};" : "=l"(r) : "f"(lo), "f"(hi)); return r;
}
__device__ __forceinline__ void fma2(u64& a, u64 b, u64 c) {
    asm("fma.rn.f32x2 %0,%1,%2,%0;" : "+l"(a) : "l"(b), "l"(c));
}
__device__ __forceinline__ void unpk(u64 p, float& lo, float& hi) {
    asm("mov.b64 {%0,%1},%2;" : "=f"(lo), "=f"(hi) : "l"(p));
}

// ---- quantized weight scratch ---------------------------------------------
__device__ __align__(16) float g_qc1wp[280];   // 10 x 28 (25 taps + pad), q8
__device__ float g_qc1b[10];
__device__ __align__(16) float g_qc2wp[5600];  // 20 x 10 x 28, q8
__device__ float g_qc2b[20];
__device__ __align__(16) float g_qf1wT[16640]; // 320 x 52 transposed, clip(q8)
__device__ float g_qf1b[50];
__device__ __align__(16) float g_qf2w[500];    // 10 x 50, clip(q8)
__device__ float g_qf2b[10];

// ---------------------------------------------------------------------------
__global__ void k_quant_weights(const float* __restrict__ c1w, const float* __restrict__ c1b,
                                const float* __restrict__ c2w, const float* __restrict__ c2b,
                                const float* __restrict__ f1w, const float* __restrict__ f1b,
                                const float* __restrict__ f2w, const float* __restrict__ f2b)
{
    int i = blockIdx.x * blockDim.x + threadIdx.x;
    if (i < 280) {
        int j = i / 28, t = i % 28;
        g_qc1wp[i] = (t < 25) ? q8(c1w[j * 25 + t]) : 0.f;
    } else if (i < 290) {
        g_qc1b[i - 280] = q8(c1b[i - 280]);
    } else if (i < 5890) {
        int r = i - 290;
        int jc = r / 28, t = r % 28;
        g_qc2wp[r] = (t < 25) ? q8(c2w[jc * 25 + t]) : 0.f;
    } else if (i < 5910) {
        g_qc2b[i - 5890] = q8(c2b[i - 5890]);
    } else if (i < 22550) {
        int r = i - 5910;
        int k = r / 52, l = r % 52;
        g_qf1wT[r] = (l < 50) ? clipf(q8(f1w[l * 320 + k])) : 0.f;
    } else if (i < 22600) {
        g_qf1b[i - 22550] = clipf(q8(f1b[i - 22550]));
    } else if (i < 23100) {
        g_qf2w[i - 22600] = clipf(q8(f2w[i - 22600]));
    } else if (i < 23110) {
        g_qf2b[i - 23100] = clipf(q8(f2b[i - 23100]));
    }
}

// ---- smem layout (floats) --------------------------------------------------
// XI: 28 rows x 36 (32 interleaved + 4 pad). XI[r][2k]=x[k], XI[r][2k+1]=x[k+12].
// P1 interleaved (R14): per channel 12 rows x 20; row L[2k]=col k, L[2k+1]=col k+4.
//   channel stride 244 for distinct (ph,chalf) bank phases.
#define XI_ROW   36
#define P1_ROW   20
#define P1_CH    244
#define S_XI   0        // 1008           (aliased by fc scratch after conv1)
#define S_P1   1008     // 10 ch x 244 = 2440
#define S_P2   3448     // 320
#define S_TOT  3768     // 15072 bytes
// fc scratch aliases S_XI:
#define S_PART 0        // [2 slices][52]
#define S_H1   104      // [52]
#define S_Z    160      // [12]

// Load 25 padded taps (7 float4) from gmem into registers.
__device__ __forceinline__ void load_w25(const float* gw, float* wr)
{
    const float4* w4 = (const float4*)gw;
    float wf[28];
    #pragma unroll
    for (int q = 0; q < 7; q++) {
        float4 t = __ldg(w4 + q);
        wf[q*4+0]=t.x; wf[q*4+1]=t.y; wf[q*4+2]=t.z; wf[q*4+3]=t.w;
    }
    #pragma unroll
    for (int q = 0; q < 25; q++) wr[q] = wf[q];
}

// ---------------------------------------------------------------------------
__global__ __launch_bounds__(NTHR) void k_fused(const float* __restrict__ x,
                                                float* __restrict__ out)
{
    __shared__ __align__(16) float sm[S_TOT];
    const int tid = threadIdx.x;
    const int blk = blockIdx.x;

    // ---- stage 0: quantized input to smem, interleaved {k, k+12} ----------
    {
        const float* xin = x + (size_t)blk * 784;
        for (int i = tid; i < 784; i += NTHR) {
            const int r = i / 28, k = i % 28;
            const float v = q8(xin[i]);
            float* Xr = sm + S_XI + r * XI_ROW;
            if (k < 16)  Xr[2 * k] = v;
            if (k >= 12) Xr[2 * (k - 12) + 1] = v;
        }
    }
    __syncthreads();

    // ---- stage 1: conv1 + pool + relu -> interleaved P1 (column-pair FFMA2)
    // thread = (j in 10, tt in 16); unit = (ph in 12, p in 6) -> pooled {p, p+6}.
    {
        const int j  = tid / 16;
        const int tt = tid % 16;
        float wr[25];
        load_w25(g_qc1wp + j * 28, wr);
        const float bj = __ldg(&g_qc1b[j]);
        float* chan = sm + S_P1 + j * P1_CH;

        #pragma unroll
        for (int qq = 0; qq < 5; qq++) {
            const int q = tt + 16 * qq;          // 0..79, guard <72
            if (q < 72) {
                const int ph = q / 6, p = q % 6;
                const int r0 = 2 * ph;

                u64 AT0, AT1, AB0, AB1;
                AT0 = AT1 = AB0 = AB1 = pk(0.f, 0.f);

                #pragma unroll
                for (int r = 0; r < 6; r++) {
                    // u64 pairs at indices 2p .. 2p+5 (16B-aligned at 2p even)
                    const ulonglong2* vp =
                        (const ulonglong2*)(sm + S_XI + (r0 + r) * XI_ROW + 4 * p);
                    ulonglong2 q0 = vp[0], q1 = vp[1], q2 = vp[2];
                    u64 P[6] = {q0.x, q0.y, q1.x, q1.y, q2.x, q2.y};
                    #pragma unroll
                    for (int v = 0; v < 5; v++) {
                        const float wt = (r < 5)  ? wr[r * 5 + v]       : 0.f;
                        const float wb = (r >= 1) ? wr[(r - 1) * 5 + v] : 0.f;
                        const u64 wtp = pk(wt, wt);
                        const u64 wbp = pk(wb, wb);
                        fma2(AT0, wtp, P[v]);
                        fma2(AT1, wtp, P[v + 1]);
                        fma2(AB0, wbp, P[v]);
                        fma2(AB1, wbp, P[v + 1]);
                    }
                }
                float t0l, t0h, t1l, t1h, b0l, b0h, b1l, b1h;
                unpk(AT0, t0l, t0h); unpk(AT1, t1l, t1h);
                unpk(AB0, b0l, b0h); unpk(AB1, b1l, b1h);
                // lo halves = conv cols {2p, 2p+1} -> pooled col p
                // hi halves = conv cols {2p+12, 2p+13} -> pooled col p+6
                float mA = fmaxf(fmaxf(t0l, t1l), fmaxf(b0l, b1l)) + bj;
                float mB = fmaxf(fmaxf(t0h, t1h), fmaxf(b0h, b1h)) + bj;
                mA = fmaxf(mA, 0.f);
                mB = fmaxf(mB, 0.f);
                // interleaved store: col c -> L[2c] (c<8) and L[2(c-4)+1] (c>=4)
                float* L = chan + ph * P1_ROW;
                L[2 * p] = mA;                       // cA = p (0..5)
                if (p >= 4) L[2 * (p - 4) + 1] = mA;
                if (p < 2)  L[2 * (p + 6)] = mB;     // cB = p+6 (6..11)
                L[2 * (p + 2) + 1] = mB;
            }
        }
    }
    __syncthreads();

    // ---- stage 2: conv2 + pool + relu + q8 (R14 column-pair FFMA2) --------
    // thread = (oc in 20, ph in 4, chalf in 2); full 4 pooled cols per thread.
    {
        const int oc    = tid >> 3;
        const int pp    = tid & 7;
        const int ph    = pp >> 1;
        const int chalf = pp & 1;            // lane^1 flips chalf
        const int r0    = 2 * ph;

        u64 AT[4], AB[4];
        #pragma unroll
        for (int z = 0; z < 4; z++) { AT[z] = pk(0.f, 0.f); AB[z] = pk(0.f, 0.f); }

        #pragma unroll 1
        for (int cc = 0; cc < 5; cc++) {
            const int c = chalf * 5 + cc;
            float wr[25];
            load_w25(g_qc2wp + (oc * 10 + c) * 28, wr);
            const float* base = sm + S_P1 + c * P1_CH + r0 * P1_ROW;
            #pragma unroll
            for (int r = 0; r < 6; r++) {
                const ulonglong2* vp = (const ulonglong2*)(base + r * P1_ROW);
                ulonglong2 q0 = vp[0], q1 = vp[1], q2 = vp[2], q3 = vp[3];
                u64 P[8] = {q0.x, q0.y, q1.x, q1.y, q2.x, q2.y, q3.x, q3.y};
                #pragma unroll
                for (int v = 0; v < 5; v++) {
                    const float wt = (r < 5)  ? wr[r * 5 + v]       : 0.f;
                    const float wb = (r >= 1) ? wr[(r - 1) * 5 + v] : 0.f;
                    const u64 wtp = pk(wt, wt);
                    const u64 wbp = pk(wb, wb);
                    #pragma unroll
                    for (int cp = 0; cp < 4; cp++) {
                        fma2(AT[cp], wtp, P[cp + v]);
                        fma2(AB[cp], wbp, P[cp + v]);
                    }
                }
            }
        }
        // merge channel halves across lane^1 (component-wise float adds)
        #pragma unroll
        for (int z = 0; z < 4; z++) {
            float lo, hi, plo, phi;
            unpk(AT[z], lo, hi);
            plo = __shfl_xor_sync(0xFFFFFFFFu, lo, 1);
            phi = __shfl_xor_sync(0xFFFFFFFFu, hi, 1);
            AT[z] = pk(lo + plo, hi + phi);
            unpk(AB[z], lo, hi);
            plo = __shfl_xor_sync(0xFFFFFFFFu, lo, 1);
            phi = __shfl_xor_sync(0xFFFFFFFFu, hi, 1);
            AB[z] = pk(lo + plo, hi + phi);
        }

        if (chalf == 0) {
            const float bj = __ldg(&g_qc2b[oc]);
            float t0l,t0h,t1l,t1h,t2l,t2h,t3l,t3h;
            float b0l,b0h,b1l,b1h,b2l,b2h,b3l,b3h;
            unpk(AT[0], t0l, t0h); unpk(AT[1], t1l, t1h);
            unpk(AT[2], t2l, t2h); unpk(AT[3], t3l, t3h);
            unpk(AB[0], b0l, b0h); unpk(AB[1], b1l, b1h);
            unpk(AB[2], b2l, b2h); unpk(AB[3], b3l, b3h);
            // pooled col 0: conv cols 0,1 | col 1: 2,3 | col 2: 4,5 | col 3: 6,7
            float m0 = fmaxf(fmaxf(t0l, t1l), fmaxf(b0l, b1l)) + bj;
            float m1 = fmaxf(fmaxf(t2l, t3l), fmaxf(b2l, b3l)) + bj;
            float m2 = fmaxf(fmaxf(t0h, t1h), fmaxf(b0h, b1h)) + bj;
            float m3 = fmaxf(fmaxf(t2h, t3h), fmaxf(b2h, b3h)) + bj;
            float* o = sm + S_P2 + oc * 16 + ph * 4;
            o[0] = q8(fmaxf(m0, 0.f));
            o[1] = q8(fmaxf(m1, 0.f));
            o[2] = q8(fmaxf(m2, 0.f));
            o[3] = q8(fmaxf(m3, 0.f));
        }
    }
    __syncthreads();

    // ---- stage 3: fc1 partials (k-split x2) -------------------------------
    if (tid < 100) {
        const int l = tid % 50;
        const int s = tid / 50;
        const float* wT = g_qf1wT + l;
        const float* p2 = sm + S_P2;
        float acc = 0.f;
        const int k0 = 160 * s;
        #pragma unroll 4
        for (int k = k0; k < k0 + 160; k++)
            acc = fmaf(__ldg(wT + k * 52), p2[k], acc);
        sm[S_PART + s * 52 + l] = acc;
    }
    __syncthreads();

    // ---- stage 4: fc1 reduce + clip/relu/q8 -------------------------------
    if (tid < 50) {
        float acc = sm[S_PART + tid] + sm[S_PART + 52 + tid];
        float h = clipf(acc + __ldg(&g_qf1b[tid]));
        h = fmaxf(h, 0.f);
        sm[S_H1 + tid] = q8(h);
    }
    __syncthreads();

    // ---- stage 5: fc2 + clip ---------------------------------------------
    if (tid < 10) {
        const float* w = g_qf2w + tid * 50;
        float acc = 0.f;
        #pragma unroll
        for (int k = 0; k < 50; k++) acc = fmaf(__ldg(w + k), sm[S_H1 + k], acc);
        sm[S_Z + tid] = clipf(acc + __ldg(&g_qf2b[tid]));
    }
    __syncthreads();

    // ---- stage 6: log_softmax --------------------------------------------
    if (tid < 10) {
        const float* z = sm + S_Z;
        float m = -1e30f;
        #pragma unroll
        for (int k = 0; k < 10; k++) m = fmaxf(m, z[k]);
        float s = 0.f;
        #pragma unroll
        for (int k = 0; k < 10; k++) s += expf(z[k] - m);
        out[blk * 10 + tid] = z[tid] - m - logf(s);
    }
}

// ---------------------------------------------------------------------------
extern "C" void kernel_launch(void* const* d_in, const int* in_sizes, int n_in,
                              void* d_out, int out_size)
{
    const float* x   = (const float*)d_in[0];
    const float* c1w = (const float*)d_in[1];
    const float* c1b = (const float*)d_in[2];
    const float* c2w = (const float*)d_in[3];
    const float* c2b = (const float*)d_in[4];
    const float* f1w = (const float*)d_in[5];
    const float* f1b = (const float*)d_in[6];
    const float* f2w = (const float*)d_in[7];
    const float* f2b = (const float*)d_in[8];
    float* out = (float*)d_out;

    k_quant_weights<<<(23110 + 255) / 256, 256>>>(c1w, c1b, c2w, c2b, f1w, f1b, f2w, f2b);
    k_fused<<<B, NTHR>>>(x, out);
}

// round 16
// speedup vs baseline: 1.1845x; 1.1845x over previous
#include <cuda_runtime.h>
#include <cuda_bf16.h>
#include <math.h>

// Fused quantized LeNet, round 16: R14 (ties best @36.9us: scalar conv1 +
// bank-fixed column-pair FFMA2 conv2) with ONE change: __launch_bounds__(160,8)
// caps regs 56->48 so 8 blocks/SM fit instead of 7 (occ 54.4% -> 62.5%).
// The kernel is latency-mixed (no pipe saturated); eligible warps bind.
// Conv per-product clip never fires (|w*x| <= ~13 << 255): convs pure FMA.

#define B        1024
#define NTHR     160

typedef unsigned long long u64;

__device__ __forceinline__ float q8(float x) {
    return rintf(x * 256.0f) * 0.00390625f;   // round-half-even, scale 2^-8
}
__device__ __forceinline__ float clipf(float x) {
    return fminf(fmaxf(x, -256.0f), 255.0f);
}
__device__ __forceinline__ u64 pk(float lo, float hi) {
    u64 r; asm("mov.b64 %0,{%1,%2};" : "=l"(r) : "f"(lo), "f"(hi)); return r;
}
__device__ __forceinline__ void fma2(u64& a, u64 b, u64 c) {
    asm("fma.rn.f32x2 %0,%1,%2,%0;" : "+l"(a) : "l"(b), "l"(c));
}
__device__ __forceinline__ void unpk(u64 p, float& lo, float& hi) {
    asm("mov.b64 {%0,%1},%2;" : "=f"(lo), "=f"(hi) : "l"(p));
}

// ---- quantized weight scratch ---------------------------------------------
__device__ __align__(16) float g_qc1wp[280];   // 10 x 28 (25 taps + pad), q8
__device__ float g_qc1b[10];
__device__ __align__(16) float g_qc2wp[5600];  // 20 x 10 x 28, q8
__device__ float g_qc2b[20];
__device__ __align__(16) float g_qf1wT[16640]; // 320 x 52 transposed, clip(q8)
__device__ float g_qf1b[50];
__device__ __align__(16) float g_qf2w[500];    // 10 x 50, clip(q8)
__device__ float g_qf2b[10];

// ---------------------------------------------------------------------------
__global__ void k_quant_weights(const float* __restrict__ c1w, const float* __restrict__ c1b,
                                const float* __restrict__ c2w, const float* __restrict__ c2b,
                                const float* __restrict__ f1w, const float* __restrict__ f1b,
                                const float* __restrict__ f2w, const float* __restrict__ f2b)
{
    int i = blockIdx.x * blockDim.x + threadIdx.x;
    if (i < 280) {
        int j = i / 28, t = i % 28;
        g_qc1wp[i] = (t < 25) ? q8(c1w[j * 25 + t]) : 0.f;
    } else if (i < 290) {
        g_qc1b[i - 280] = q8(c1b[i - 280]);
    } else if (i < 5890) {
        int r = i - 290;
        int jc = r / 28, t = r % 28;
        g_qc2wp[r] = (t < 25) ? q8(c2w[jc * 25 + t]) : 0.f;
    } else if (i < 5910) {
        g_qc2b[i - 5890] = q8(c2b[i - 5890]);
    } else if (i < 22550) {
        int r = i - 5910;
        int k = r / 52, l = r % 52;
        g_qf1wT[r] = (l < 50) ? clipf(q8(f1w[l * 320 + k])) : 0.f;
    } else if (i < 22600) {
        g_qf1b[i - 22550] = clipf(q8(f1b[i - 22550]));
    } else if (i < 23100) {
        g_qf2w[i - 22600] = clipf(q8(f2w[i - 22600]));
    } else if (i < 23110) {
        g_qf2b[i - 23100] = clipf(q8(f2b[i - 23100]));
    }
}

// ---- smem layout (floats) --------------------------------------------------
// P1 interleaved: per channel 12 rows x 20 floats (16 data + 4 pad);
//   row: L[2k] = pool1 col k (k=0..7), L[2k+1] = col k+4 (cols 4..11).
//   channel stride 244: chalf phase 1220 % 32 = 4 -> distinct bank phases.
#define P1_ROW   20
#define P1_CH    244
#define S_XQ   0        // 784            (aliased by fc scratch after conv1)
#define S_P1   784      // 10 ch x 244 = 2440
#define S_P2   3224     // 320
#define S_TOT  3544     // 14176 bytes
// fc scratch aliases S_XQ:
#define S_PART 0        // [2 slices][52]
#define S_H1   104      // [52]
#define S_Z    160      // [12]

// Load 25 padded taps (7 float4) from gmem into registers.
__device__ __forceinline__ void load_w25(const float* gw, float* wr)
{
    const float4* w4 = (const float4*)gw;
    float wf[28];
    #pragma unroll
    for (int q = 0; q < 7; q++) {
        float4 t = __ldg(w4 + q);
        wf[q*4+0]=t.x; wf[q*4+1]=t.y; wf[q*4+2]=t.z; wf[q*4+3]=t.w;
    }
    #pragma unroll
    for (int q = 0; q < 25; q++) wr[q] = wf[q];
}

// ---------------------------------------------------------------------------
__global__ __launch_bounds__(NTHR, 8) void k_fused(const float* __restrict__ x,
                                                   float* __restrict__ out)
{
    __shared__ __align__(16) float sm[S_TOT];
    const int tid = threadIdx.x;
    const int blk = blockIdx.x;

    // ---- stage 0: quantized input to smem ---------------------------------
    {
        const float* xin = x + (size_t)blk * 784;
        for (int i = tid; i < 784; i += NTHR) sm[S_XQ + i] = q8(xin[i]);
    }
    __syncthreads();

    // ---- stage 1: conv1 + pool + relu -> interleaved P1 (R5 compute) ------
    {
        const int j  = tid / 16;
        const int tt = tid % 16;
        float wr[25];
        load_w25(g_qc1wp + j * 28, wr);
        const float bj = __ldg(&g_qc1b[j]);
        const float* xb = sm + S_XQ;
        float* chan = sm + S_P1 + j * P1_CH;

        #pragma unroll
        for (int qq = 0; qq < 5; qq++) {
            const int q = tt + 16 * qq;          // 0..79, guard <72
            if (q < 72) {
                const int ph = q / 6, pwp = q % 6;
                const int r0 = 2 * ph, cb = 4 * pwp;

                float a[8];
                #pragma unroll
                for (int z = 0; z < 8; z++) a[z] = 0.f;

                #pragma unroll
                for (int r = 0; r < 6; r++) {
                    const float* rp = xb + (r0 + r) * 28 + cb;
                    float4 A = *(const float4*)rp;
                    float4 C = *(const float4*)(rp + 4);
                    float row[8] = {A.x, A.y, A.z, A.w, C.x, C.y, C.z, C.w};
                    if (r < 5) {
                        #pragma unroll
                        for (int v = 0; v < 5; v++) {
                            const float wv = wr[r * 5 + v];
                            a[0] = fmaf(wv, row[v],     a[0]);
                            a[1] = fmaf(wv, row[v + 1], a[1]);
                            a[4] = fmaf(wv, row[v + 2], a[4]);
                            a[5] = fmaf(wv, row[v + 3], a[5]);
                        }
                    }
                    if (r >= 1) {
                        #pragma unroll
                        for (int v = 0; v < 5; v++) {
                            const float wv = wr[(r - 1) * 5 + v];
                            a[2] = fmaf(wv, row[v],     a[2]);
                            a[3] = fmaf(wv, row[v + 1], a[3]);
                            a[6] = fmaf(wv, row[v + 2], a[6]);
                            a[7] = fmaf(wv, row[v + 3], a[7]);
                        }
                    }
                }
                float m0 = fmaxf(fmaxf(a[0], a[1]), fmaxf(a[2], a[3])) + bj;
                float m1 = fmaxf(fmaxf(a[4], a[5]), fmaxf(a[6], a[7])) + bj;
                m0 = fmaxf(m0, 0.f);
                m1 = fmaxf(m1, 0.f);
                // interleaved store: col c -> L[2c] (c<8) and L[2(c-4)+1] (c>=4)
                float* L = chan + ph * P1_ROW;
                const int c0 = 2 * pwp, c1 = c0 + 1;
                if (c0 < 8)  L[2 * c0] = m0;
                if (c0 >= 4) L[2 * (c0 - 4) + 1] = m0;
                if (c1 < 8)  L[2 * c1] = m1;
                if (c1 >= 4) L[2 * (c1 - 4) + 1] = m1;
            }
        }
    }
    __syncthreads();

    // ---- stage 2: conv2 + pool + relu + q8 (column-pair FFMA2) ------------
    // thread = (oc in 20, ph in 4, chalf in 2); full 4 pooled cols per thread.
    {
        const int oc    = tid >> 3;
        const int pp    = tid & 7;
        const int ph    = pp >> 1;
        const int chalf = pp & 1;            // lane^1 flips chalf
        const int r0    = 2 * ph;

        u64 AT[4], AB[4];
        #pragma unroll
        for (int z = 0; z < 4; z++) { AT[z] = pk(0.f, 0.f); AB[z] = pk(0.f, 0.f); }

        #pragma unroll 1
        for (int cc = 0; cc < 5; cc++) {
            const int c = chalf * 5 + cc;
            float wr[25];
            load_w25(g_qc2wp + (oc * 10 + c) * 28, wr);
            const float* base = sm + S_P1 + c * P1_CH + r0 * P1_ROW;
            #pragma unroll
            for (int r = 0; r < 6; r++) {
                const ulonglong2* vp = (const ulonglong2*)(base + r * P1_ROW);
                ulonglong2 q0 = vp[0], q1 = vp[1], q2 = vp[2], q3 = vp[3];
                u64 P[8] = {q0.x, q0.y, q1.x, q1.y, q2.x, q2.y, q3.x, q3.y};
                #pragma unroll
                for (int v = 0; v < 5; v++) {
                    const float wt = (r < 5)  ? wr[r * 5 + v]       : 0.f;
                    const float wb = (r >= 1) ? wr[(r - 1) * 5 + v] : 0.f;
                    const u64 wtp = pk(wt, wt);
                    const u64 wbp = pk(wb, wb);
                    #pragma unroll
                    for (int cp = 0; cp < 4; cp++) {
                        fma2(AT[cp], wtp, P[cp + v]);
                        fma2(AB[cp], wbp, P[cp + v]);
                    }
                }
            }
        }
        // merge channel halves across lane^1 (component-wise float adds)
        #pragma unroll
        for (int z = 0; z < 4; z++) {
            float lo, hi, plo, phi;
            unpk(AT[z], lo, hi);
            plo = __shfl_xor_sync(0xFFFFFFFFu, lo, 1);
            phi = __shfl_xor_sync(0xFFFFFFFFu, hi, 1);
            AT[z] = pk(lo + plo, hi + phi);
            unpk(AB[z], lo, hi);
            plo = __shfl_xor_sync(0xFFFFFFFFu, lo, 1);
            phi = __shfl_xor_sync(0xFFFFFFFFu, hi, 1);
            AB[z] = pk(lo + plo, hi + phi);
        }

        if (chalf == 0) {
            const float bj = __ldg(&g_qc2b[oc]);
            float t0l,t0h,t1l,t1h,t2l,t2h,t3l,t3h;
            float b0l,b0h,b1l,b1h,b2l,b2h,b3l,b3h;
            unpk(AT[0], t0l, t0h); unpk(AT[1], t1l, t1h);
            unpk(AT[2], t2l, t2h); unpk(AT[3], t3l, t3h);
            unpk(AB[0], b0l, b0h); unpk(AB[1], b1l, b1h);
            unpk(AB[2], b2l, b2h); unpk(AB[3], b3l, b3h);
            // pooled col 0: conv cols 0,1 | col 1: 2,3 | col 2: 4,5 | col 3: 6,7
            float m0 = fmaxf(fmaxf(t0l, t1l), fmaxf(b0l, b1l)) + bj;
            float m1 = fmaxf(fmaxf(t2l, t3l), fmaxf(b2l, b3l)) + bj;
            float m2 = fmaxf(fmaxf(t0h, t1h), fmaxf(b0h, b1h)) + bj;
            float m3 = fmaxf(fmaxf(t2h, t3h), fmaxf(b2h, b3h)) + bj;
            float* o = sm + S_P2 + oc * 16 + ph * 4;
            o[0] = q8(fmaxf(m0, 0.f));
            o[1] = q8(fmaxf(m1, 0.f));
            o[2] = q8(fmaxf(m2, 0.f));
            o[3] = q8(fmaxf(m3, 0.f));
        }
    }
    __syncthreads();

    // ---- stage 3: fc1 partials (k-split x2) -------------------------------
    if (tid < 100) {
        const int l = tid % 50;
        const int s = tid / 50;
        const float* wT = g_qf1wT + l;
        const float* p2 = sm + S_P2;
        float acc = 0.f;
        const int k0 = 160 * s;
        #pragma unroll 4
        for (int k = k0; k < k0 + 160; k++)
            acc = fmaf(__ldg(wT + k * 52), p2[k], acc);
        sm[S_PART + s * 52 + l] = acc;
    }
    __syncthreads();

    // ---- stage 4: fc1 reduce + clip/relu/q8 -------------------------------
    if (tid < 50) {
        float acc = sm[S_PART + tid] + sm[S_PART + 52 + tid];
        float h = clipf(acc + __ldg(&g_qf1b[tid]));
        h = fmaxf(h, 0.f);
        sm[S_H1 + tid] = q8(h);
    }
    __syncthreads();

    // ---- stage 5: fc2 + clip ---------------------------------------------
    if (tid < 10) {
        const float* w = g_qf2w + tid * 50;
        float acc = 0.f;
        #pragma unroll
        for (int k = 0; k < 50; k++) acc = fmaf(__ldg(w + k), sm[S_H1 + k], acc);
        sm[S_Z + tid] = clipf(acc + __ldg(&g_qf2b[tid]));
    }
    __syncthreads();

    // ---- stage 6: log_softmax --------------------------------------------
    if (tid < 10) {
        const float* z = sm + S_Z;
        float m = -1e30f;
        #pragma unroll
        for (int k = 0; k < 10; k++) m = fmaxf(m, z[k]);
        float s = 0.f;
        #pragma unroll
        for (int k = 0; k < 10; k++) s += expf(z[k] - m);
        out[blk * 10 + tid] = z[tid] - m - logf(s);
    }
}

// ---------------------------------------------------------------------------
extern "C" void kernel_launch(void* const* d_in, const int* in_sizes, int n_in,
                              void* d_out, int out_size)
{
    const float* x   = (const float*)d_in[0];
    const float* c1w = (const float*)d_in[1];
    const float* c1b = (const float*)d_in[2];
    const float* c2w = (const float*)d_in[3];
    const float* c2b = (const float*)d_in[4];
    const float* f1w = (const float*)d_in[5];
    const float* f1b = (const float*)d_in[6];
    const float* f2w = (const float*)d_in[7];
    const float* f2b = (const float*)d_in[8];
    float* out = (float*)d_out;

    k_quant_weights<<<(23110 + 255) / 256, 256>>>(c1w, c1b, c2w, c2b, f1w, f1b, f2w, f2b);
    k_fused<<<B, NTHR>>>(x, out);
}

// round 17
// speedup vs baseline: 1.1917x; 1.0061x over previous
#include <cuda_runtime.h>
#include <cuda_bf16.h>
#include <math.h>

// Fused quantized LeNet, round 17: R14 chassis (best, 36.9us: scalar conv1 +
// bank-fixed column-pair FFMA2 conv2) + shortened serial tail:
//   - fc1 k-split 2->3 slices (150 threads, chain 160->107 iters)
//   - stages 4-6 run under 2-warp named barriers (bar.sync 1,64); warps 2-4
//     exit after stage 3 instead of hitting 3 more block-wide barriers.
// Conv per-product clip never fires (|w*x| <= ~13 << 255): convs pure FMA.

#define B        1024
#define NTHR     160

typedef unsigned long long u64;

__device__ __forceinline__ float q8(float x) {
    return rintf(x * 256.0f) * 0.00390625f;   // round-half-even, scale 2^-8
}
__device__ __forceinline__ float clipf(float x) {
    return fminf(fmaxf(x, -256.0f), 255.0f);
}
__device__ __forceinline__ u64 pk(float lo, float hi) {
    u64 r; asm("mov.b64 %0,{%1,%2};" : "=l"(r) : "f"(lo), "f"(hi)); return r;
}
__device__ __forceinline__ void fma2(u64& a, u64 b, u64 c) {
    asm("fma.rn.f32x2 %0,%1,%2,%0;" : "+l"(a) : "l"(b), "l"(c));
}
__device__ __forceinline__ void unpk(u64 p, float& lo, float& hi) {
    asm("mov.b64 {%0,%1},%2;" : "=f"(lo), "=f"(hi) : "l"(p));
}

// ---- quantized weight scratch ---------------------------------------------
__device__ __align__(16) float g_qc1wp[280];   // 10 x 28 (25 taps + pad), q8
__device__ float g_qc1b[10];
__device__ __align__(16) float g_qc2wp[5600];  // 20 x 10 x 28, q8
__device__ float g_qc2b[20];
__device__ __align__(16) float g_qf1wT[16640]; // 320 x 52 transposed, clip(q8)
__device__ float g_qf1b[50];
__device__ __align__(16) float g_qf2w[500];    // 10 x 50, clip(q8)
__device__ float g_qf2b[10];

// ---------------------------------------------------------------------------
__global__ void k_quant_weights(const float* __restrict__ c1w, const float* __restrict__ c1b,
                                const float* __restrict__ c2w, const float* __restrict__ c2b,
                                const float* __restrict__ f1w, const float* __restrict__ f1b,
                                const float* __restrict__ f2w, const float* __restrict__ f2b)
{
    int i = blockIdx.x * blockDim.x + threadIdx.x;
    if (i < 280) {
        int j = i / 28, t = i % 28;
        g_qc1wp[i] = (t < 25) ? q8(c1w[j * 25 + t]) : 0.f;
    } else if (i < 290) {
        g_qc1b[i - 280] = q8(c1b[i - 280]);
    } else if (i < 5890) {
        int r = i - 290;
        int jc = r / 28, t = r % 28;
        g_qc2wp[r] = (t < 25) ? q8(c2w[jc * 25 + t]) : 0.f;
    } else if (i < 5910) {
        g_qc2b[i - 5890] = q8(c2b[i - 5890]);
    } else if (i < 22550) {
        int r = i - 5910;
        int k = r / 52, l = r % 52;
        g_qf1wT[r] = (l < 50) ? clipf(q8(f1w[l * 320 + k])) : 0.f;
    } else if (i < 22600) {
        g_qf1b[i - 22550] = clipf(q8(f1b[i - 22550]));
    } else if (i < 23100) {
        g_qf2w[i - 22600] = clipf(q8(f2w[i - 22600]));
    } else if (i < 23110) {
        g_qf2b[i - 23100] = clipf(q8(f2b[i - 23100]));
    }
}

// ---- smem layout (floats) --------------------------------------------------
// P1 interleaved: per channel 12 rows x 20 floats (16 data + 4 pad);
//   row: L[2k] = pool1 col k (k=0..7), L[2k+1] = col k+4 (cols 4..11).
//   channel stride 244: chalf phase 1220 % 32 = 4 -> distinct bank phases.
#define P1_ROW   20
#define P1_CH    244
#define S_XQ   0        // 784            (aliased by fc scratch after conv1)
#define S_P1   784      // 10 ch x 244 = 2440
#define S_P2   3224     // 320
#define S_TOT  3544     // 14176 bytes
// fc scratch aliases S_XQ:
#define S_PART 0        // [3 slices][52]
#define S_H1   156      // [52]
#define S_Z    212      // [12]

// Load 25 padded taps (7 float4) from gmem into registers.
__device__ __forceinline__ void load_w25(const float* gw, float* wr)
{
    const float4* w4 = (const float4*)gw;
    float wf[28];
    #pragma unroll
    for (int q = 0; q < 7; q++) {
        float4 t = __ldg(w4 + q);
        wf[q*4+0]=t.x; wf[q*4+1]=t.y; wf[q*4+2]=t.z; wf[q*4+3]=t.w;
    }
    #pragma unroll
    for (int q = 0; q < 25; q++) wr[q] = wf[q];
}

// ---------------------------------------------------------------------------
__global__ __launch_bounds__(NTHR) void k_fused(const float* __restrict__ x,
                                                float* __restrict__ out)
{
    __shared__ __align__(16) float sm[S_TOT];
    const int tid = threadIdx.x;
    const int blk = blockIdx.x;

    // ---- stage 0: quantized input to smem ---------------------------------
    {
        const float* xin = x + (size_t)blk * 784;
        for (int i = tid; i < 784; i += NTHR) sm[S_XQ + i] = q8(xin[i]);
    }
    __syncthreads();

    // ---- stage 1: conv1 + pool + relu -> interleaved P1 (R5 compute) ------
    {
        const int j  = tid / 16;
        const int tt = tid % 16;
        float wr[25];
        load_w25(g_qc1wp + j * 28, wr);
        const float bj = __ldg(&g_qc1b[j]);
        const float* xb = sm + S_XQ;
        float* chan = sm + S_P1 + j * P1_CH;

        #pragma unroll
        for (int qq = 0; qq < 5; qq++) {
            const int q = tt + 16 * qq;          // 0..79, guard <72
            if (q < 72) {
                const int ph = q / 6, pwp = q % 6;
                const int r0 = 2 * ph, cb = 4 * pwp;

                float a[8];
                #pragma unroll
                for (int z = 0; z < 8; z++) a[z] = 0.f;

                #pragma unroll
                for (int r = 0; r < 6; r++) {
                    const float* rp = xb + (r0 + r) * 28 + cb;
                    float4 A = *(const float4*)rp;
                    float4 C = *(const float4*)(rp + 4);
                    float row[8] = {A.x, A.y, A.z, A.w, C.x, C.y, C.z, C.w};
                    if (r < 5) {
                        #pragma unroll
                        for (int v = 0; v < 5; v++) {
                            const float wv = wr[r * 5 + v];
                            a[0] = fmaf(wv, row[v],     a[0]);
                            a[1] = fmaf(wv, row[v + 1], a[1]);
                            a[4] = fmaf(wv, row[v + 2], a[4]);
                            a[5] = fmaf(wv, row[v + 3], a[5]);
                        }
                    }
                    if (r >= 1) {
                        #pragma unroll
                        for (int v = 0; v < 5; v++) {
                            const float wv = wr[(r - 1) * 5 + v];
                            a[2] = fmaf(wv, row[v],     a[2]);
                            a[3] = fmaf(wv, row[v + 1], a[3]);
                            a[6] = fmaf(wv, row[v + 2], a[6]);
                            a[7] = fmaf(wv, row[v + 3], a[7]);
                        }
                    }
                }
                float m0 = fmaxf(fmaxf(a[0], a[1]), fmaxf(a[2], a[3])) + bj;
                float m1 = fmaxf(fmaxf(a[4], a[5]), fmaxf(a[6], a[7])) + bj;
                m0 = fmaxf(m0, 0.f);
                m1 = fmaxf(m1, 0.f);
                // interleaved store: col c -> L[2c] (c<8) and L[2(c-4)+1] (c>=4)
                float* L = chan + ph * P1_ROW;
                const int c0 = 2 * pwp, c1 = c0 + 1;
                if (c0 < 8)  L[2 * c0] = m0;
                if (c0 >= 4) L[2 * (c0 - 4) + 1] = m0;
                if (c1 < 8)  L[2 * c1] = m1;
                if (c1 >= 4) L[2 * (c1 - 4) + 1] = m1;
            }
        }
    }
    __syncthreads();

    // ---- stage 2: conv2 + pool + relu + q8 (column-pair FFMA2) ------------
    // thread = (oc in 20, ph in 4, chalf in 2); full 4 pooled cols per thread.
    {
        const int oc    = tid >> 3;
        const int pp    = tid & 7;
        const int ph    = pp >> 1;
        const int chalf = pp & 1;            // lane^1 flips chalf
        const int r0    = 2 * ph;

        u64 AT[4], AB[4];
        #pragma unroll
        for (int z = 0; z < 4; z++) { AT[z] = pk(0.f, 0.f); AB[z] = pk(0.f, 0.f); }

        #pragma unroll 1
        for (int cc = 0; cc < 5; cc++) {
            const int c = chalf * 5 + cc;
            float wr[25];
            load_w25(g_qc2wp + (oc * 10 + c) * 28, wr);
            const float* base = sm + S_P1 + c * P1_CH + r0 * P1_ROW;
            #pragma unroll
            for (int r = 0; r < 6; r++) {
                const ulonglong2* vp = (const ulonglong2*)(base + r * P1_ROW);
                ulonglong2 q0 = vp[0], q1 = vp[1], q2 = vp[2], q3 = vp[3];
                u64 P[8] = {q0.x, q0.y, q1.x, q1.y, q2.x, q2.y, q3.x, q3.y};
                #pragma unroll
                for (int v = 0; v < 5; v++) {
                    const float wt = (r < 5)  ? wr[r * 5 + v]       : 0.f;
                    const float wb = (r >= 1) ? wr[(r - 1) * 5 + v] : 0.f;
                    const u64 wtp = pk(wt, wt);
                    const u64 wbp = pk(wb, wb);
                    #pragma unroll
                    for (int cp = 0; cp < 4; cp++) {
                        fma2(AT[cp], wtp, P[cp + v]);
                        fma2(AB[cp], wbp, P[cp + v]);
                    }
                }
            }
        }
        // merge channel halves across lane^1 (component-wise float adds)
        #pragma unroll
        for (int z = 0; z < 4; z++) {
            float lo, hi, plo, phi;
            unpk(AT[z], lo, hi);
            plo = __shfl_xor_sync(0xFFFFFFFFu, lo, 1);
            phi = __shfl_xor_sync(0xFFFFFFFFu, hi, 1);
            AT[z] = pk(lo + plo, hi + phi);
            unpk(AB[z], lo, hi);
            plo = __shfl_xor_sync(0xFFFFFFFFu, lo, 1);
            phi = __shfl_xor_sync(0xFFFFFFFFu, hi, 1);
            AB[z] = pk(lo + plo, hi + phi);
        }

        if (chalf == 0) {
            const float bj = __ldg(&g_qc2b[oc]);
            float t0l,t0h,t1l,t1h,t2l,t2h,t3l,t3h;
            float b0l,b0h,b1l,b1h,b2l,b2h,b3l,b3h;
            unpk(AT[0], t0l, t0h); unpk(AT[1], t1l, t1h);
            unpk(AT[2], t2l, t2h); unpk(AT[3], t3l, t3h);
            unpk(AB[0], b0l, b0h); unpk(AB[1], b1l, b1h);
            unpk(AB[2], b2l, b2h); unpk(AB[3], b3l, b3h);
            // pooled col 0: conv cols 0,1 | col 1: 2,3 | col 2: 4,5 | col 3: 6,7
            float m0 = fmaxf(fmaxf(t0l, t1l), fmaxf(b0l, b1l)) + bj;
            float m1 = fmaxf(fmaxf(t2l, t3l), fmaxf(b2l, b3l)) + bj;
            float m2 = fmaxf(fmaxf(t0h, t1h), fmaxf(b0h, b1h)) + bj;
            float m3 = fmaxf(fmaxf(t2h, t3h), fmaxf(b2h, b3h)) + bj;
            float* o = sm + S_P2 + oc * 16 + ph * 4;
            o[0] = q8(fmaxf(m0, 0.f));
            o[1] = q8(fmaxf(m1, 0.f));
            o[2] = q8(fmaxf(m2, 0.f));
            o[3] = q8(fmaxf(m3, 0.f));
        }
    }
    __syncthreads();

    // ---- stage 3: fc1 partials (k-split x3, 150 threads) ------------------
    if (tid < 150) {
        const int l = tid % 50;
        const int s = tid / 50;                 // 0..2
        const int k0 = (s == 0) ? 0 : (s == 1 ? 107 : 214);
        const int k1 = (s == 0) ? 107 : (s == 1 ? 214 : 320);
        const float* wT = g_qf1wT + l;
        const float* p2 = sm + S_P2;
        float acc = 0.f;
        #pragma unroll 4
        for (int k = k0; k < k1; k++)
            acc = fmaf(__ldg(wT + k * 52), p2[k], acc);
        sm[S_PART + s * 52 + l] = acc;
    }
    __syncthreads();

    // ---- stages 4-6: fc1 reduce / fc2 / softmax, 2 warps only -------------
    if (tid < 64) {
        if (tid < 50) {
            float acc = (sm[S_PART + tid] + sm[S_PART + 52 + tid])
                      + sm[S_PART + 104 + tid];
            float h = clipf(acc + __ldg(&g_qf1b[tid]));
            h = fmaxf(h, 0.f);
            sm[S_H1 + tid] = q8(h);
        }
        asm volatile("bar.sync 1, 64;" ::: "memory");

        if (tid < 10) {
            const float* w = g_qf2w + tid * 50;
            float acc = 0.f;
            #pragma unroll
            for (int k = 0; k < 50; k++)
                acc = fmaf(__ldg(w + k), sm[S_H1 + k], acc);
            sm[S_Z + tid] = clipf(acc + __ldg(&g_qf2b[tid]));
        }
        asm volatile("bar.sync 1, 64;" ::: "memory");

        if (tid < 10) {
            const float* z = sm + S_Z;
            float m = -1e30f;
            #pragma unroll
            for (int k = 0; k < 10; k++) m = fmaxf(m, z[k]);
            float s = 0.f;
            #pragma unroll
            for (int k = 0; k < 10; k++) s += expf(z[k] - m);
            out[blk * 10 + tid] = z[tid] - m - logf(s);
        }
    }
}

// ---------------------------------------------------------------------------
extern "C" void kernel_launch(void* const* d_in, const int* in_sizes, int n_in,
                              void* d_out, int out_size)
{
    const float* x   = (const float*)d_in[0];
    const float* c1w = (const float*)d_in[1];
    const float* c1b = (const float*)d_in[2];
    const float* c2w = (const float*)d_in[3];
    const float* c2b = (const float*)d_in[4];
    const float* f1w = (const float*)d_in[5];
    const float* f1b = (const float*)d_in[6];
    const float* f2w = (const float*)d_in[7];
    const float* f2b = (const float*)d_in[8];
    float* out = (float*)d_out;

    k_quant_weights<<<(23110 + 255) / 256, 256>>>(c1w, c1b, c2w, c2b, f1w, f1b, f2w, f2b);
    k_fused<<<B, NTHR>>>(x, out);
}